// round 15
// baseline (speedup 1.0000x reference)
#include <cuda_runtime.h>
#include <cuda_fp16.h>
#include <cstdint>
#include <math.h>

#define Bn   16
#define Cn   256
#define HWn  1024
#define ADn  16
#define SCn  32
#define CRn  64
#define C4n  1024
#define NPIX (Bn*HWn)   // 16384

// ======================= device scratch =======================
__device__ float g_part[Bn*8*Cn];
__device__ int   g_cnt[Bn];          // zero-init; reset by finisher each run
__device__ float g_s[Bn*Cn];
__device__ __align__(256) __half g_q[Bn*HWn*ADn];
__device__ __align__(256) __half g_k[Bn*HWn*ADn];
__device__ __align__(256) __half g_v[Bn*HWn*SCn];
__device__ __align__(256) __half g_y[NPIX*Cn];
__device__ __align__(256) __half g_h[NPIX*C4n];
__device__ __align__(256) __half g_w1[Cn*C4n];
__device__ __align__(256) __half g_w2[C4n*Cn];

// ======================= PTX helpers =======================
__device__ __forceinline__ uint32_t smem_to_u32(const void* p) {
    uint32_t a;
    asm("{ .reg .u64 t; cvta.to.shared.u64 t, %1; cvt.u32.u64 %0, t; }" : "=r"(a) : "l"(p));
    return a;
}
__device__ __forceinline__ void ldsm_x4(uint32_t r[4], uint32_t addr) {
    asm volatile("ldmatrix.sync.aligned.m8n8.x4.shared.b16 {%0,%1,%2,%3}, [%4];"
        : "=r"(r[0]), "=r"(r[1]), "=r"(r[2]), "=r"(r[3]) : "r"(addr));
}
__device__ __forceinline__ void ldsm_x4_t(uint32_t r[4], uint32_t addr) {
    asm volatile("ldmatrix.sync.aligned.m8n8.x4.trans.shared.b16 {%0,%1,%2,%3}, [%4];"
        : "=r"(r[0]), "=r"(r[1]), "=r"(r[2]), "=r"(r[3]) : "r"(addr));
}
__device__ __forceinline__ void mma_f16(float c[4], const uint32_t a[4], const uint32_t b[2]) {
    asm volatile("mma.sync.aligned.m16n8k16.row.col.f32.f16.f16.f32 "
        "{%0,%1,%2,%3}, {%4,%5,%6,%7}, {%8,%9}, {%0,%1,%2,%3};"
        : "+f"(c[0]), "+f"(c[1]), "+f"(c[2]), "+f"(c[3])
        : "r"(a[0]), "r"(a[1]), "r"(a[2]), "r"(a[3]), "r"(b[0]), "r"(b[1]));
}
#define CP_ASYNC16(dst, src) \
    asm volatile("cp.async.cg.shared.global [%0], [%1], 16;" :: "r"(dst), "l"(src))
#define CP_COMMIT() asm volatile("cp.async.commit_group;")
#define CP_WAIT(n)  asm volatile("cp.async.wait_group %0;" :: "n"(n))

__device__ __forceinline__ uint32_t pack2h(float f0, float f1) {
    __half2 h = __floats2half2_rn(f0, f1);
    return *(uint32_t*)&h;
}

// ======================= kernel 1: fused convert(512) + SE(128, atomic finisher) =====
__global__ __launch_bounds__(256) void pre_kernel(
    const float* __restrict__ w1f, const float* __restrict__ w2f,
    const float* __restrict__ x,
    const float* __restrict__ fc1_w, const float* __restrict__ fc1_b,
    const float* __restrict__ fc2_w, const float* __restrict__ fc2_b)
{
    int bid = blockIdx.x;
    int tid = threadIdx.x, lane = tid & 31, warp = tid >> 5;

    if (bid < 512) {
        // weight convert + transpose
        __shared__ float s[32][33];
        const float* w; int O, K, tk, to;
        if (bid < 256) { w = w1f; O = C4n; K = Cn;  tk = bid & 7;  to = bid >> 3; }
        else { int b2 = bid - 256; w = w2f; O = Cn; K = C4n; tk = b2 >> 3; to = b2 & 7; }
        __half* dst = (O == C4n) ? g_w1 : g_w2;
        int k0 = tk*32, o0 = to*32;
        #pragma unroll
        for (int i = tid; i < 1024; i += 256) {
            int o = i >> 5, k = i & 31;
            s[k][o] = w[(size_t)(o0 + o)*K + k0 + k];
        }
        __syncthreads();
        #pragma unroll
        for (int i = tid; i < 1024; i += 256) {
            int k = i >> 5, o = i & 31;
            dst[(size_t)(k0 + k)*O + o0 + o] = __float2half_rn(s[k][o]);
        }
        return;
    }

    // SE partial sums
    int id = bid - 512;
    int sl = id & 7, b = id >> 3;
    #pragma unroll
    for (int c = warp; c < Cn; c += 8) {
        float4 v = *(const float4*)(x + ((size_t)b*Cn + c)*HWn + sl*128 + lane*4);
        float sum = v.x + v.y + v.z + v.w;
        #pragma unroll
        for (int o = 16; o > 0; o >>= 1) sum += __shfl_xor_sync(0xffffffffu, sum, o);
        if (lane == 0) g_part[(b*8 + sl)*Cn + c] = sum;
    }
    __threadfence();
    __shared__ int is_last;
    if (tid == 0) is_last = (atomicAdd(&g_cnt[b], 1) == 7);
    __syncthreads();
    if (!is_last) return;
    if (tid == 0) g_cnt[b] = 0;      // reset for next graph replay

    // finisher: fc1 -> relu -> fc2 -> sigmoid
    __shared__ float mean[Cn];
    __shared__ float s1[CRn];
    {
        float sum = 0.f;
        #pragma unroll
        for (int s = 0; s < 8; s++) sum += g_part[(b*8 + s)*Cn + tid];
        mean[tid] = sum * (1.0f/HWn);
    }
    __syncthreads();
    #pragma unroll
    for (int i = 0; i < 8; i++) {
        int o = warp*8 + i;
        const float* wr = fc1_w + o*Cn;
        float sum = 0.f;
        #pragma unroll
        for (int j = 0; j < 8; j++) {
            int c = lane + 32*j;
            sum += wr[c]*mean[c];
        }
        #pragma unroll
        for (int off = 16; off > 0; off >>= 1) sum += __shfl_xor_sync(0xffffffffu, sum, off);
        if (lane == 0) s1[o] = fmaxf(sum + fc1_b[o], 0.f);
    }
    __syncthreads();
    #pragma unroll
    for (int i = 0; i < 32; i++) {
        int o = warp*32 + i;
        const float* wr = fc2_w + o*CRn;
        float sum = wr[lane]*s1[lane] + wr[lane+32]*s1[lane+32];
        #pragma unroll
        for (int off = 16; off > 0; off >>= 1) sum += __shfl_xor_sync(0xffffffffu, sum, off);
        if (lane == 0) g_s[b*Cn + o] = 1.f/(1.f + __expf(-(sum + fc2_b[o])));
    }
}

// ======================= kernel 2: fused gate + qkv (cp.async double-buffered) =====
__global__ __launch_bounds__(256) void gate_all_kernel(
    const float* __restrict__ x,
    const float* __restrict__ qkv_w, const float* __restrict__ qkv_b)
{
    __shared__ float t[2*32*132];
    __shared__ float ws[32][64];
    __shared__ float sgall[Cn];
    __shared__ float qb[64];

    int b = blockIdx.y, n0 = blockIdx.x*128;
    int tid = threadIdx.x;
    const uint32_t tbase = smem_to_u32(t);

    auto ISSUE_X = [&](int cg, int buf) {
        #pragma unroll
        for (int q = 0; q < 4; q++) {
            int idx = tid + q*256;
            int row = idx >> 5, seg = idx & 31;
            uint32_t dst = tbase + (uint32_t)(buf*4224 + row*132)*4 + seg*16;
            const float* src = x + ((size_t)b*Cn + cg*32 + row)*HWn + n0 + seg*4;
            CP_ASYNC16(dst, src);
        }
    };

    ISSUE_X(0, 0); CP_COMMIT();

    for (int i = tid; i < 64*SCn; i += 256) { int o = i >> 5, c = i & 31; ws[c][o] = qkv_w[i]; }
    if (tid < 64) qb[tid] = qkv_b[tid];
    sgall[tid] = g_s[b*Cn + tid];

    int p   = tid & 127;
    int sub = tid >> 7;
    size_t P = (size_t)b*HWn + n0 + p;

    for (int cg = 0; cg < 8; cg++) {
        int buf = cg & 1;
        if (cg < 7) { ISSUE_X(cg + 1, buf ^ 1); CP_COMMIT(); CP_WAIT(1); }
        else        { CP_WAIT(0); }
        __syncthreads();
        const float* tb = t + buf*4224;

        if (cg == 0) {
            float acc[32];
            #pragma unroll
            for (int o = 0; o < 32; o++) acc[o] = qb[sub*32 + o];
            #pragma unroll 4
            for (int c = 0; c < SCn; c++) {
                float xv = tb[c*132 + p] * sgall[c];
                #pragma unroll
                for (int o4 = 0; o4 < 8; o4++) {
                    float4 w = *(const float4*)&ws[c][sub*32 + o4*4];
                    acc[o4*4+0] += w.x*xv;
                    acc[o4*4+1] += w.y*xv;
                    acc[o4*4+2] += w.z*xv;
                    acc[o4*4+3] += w.w*xv;
                }
            }
            __align__(16) uint32_t pk[16];
            if (sub == 0) {
                #pragma unroll
                for (int i = 0; i < 8; i++) pk[i] = pack2h(acc[2*i]*0.25f, acc[2*i+1]*0.25f);
                #pragma unroll
                for (int i = 8; i < 16; i++) pk[i] = pack2h(acc[2*i], acc[2*i+1]);
                *(uint4*)(g_q + P*ADn)     = *(uint4*)&pk[0];
                *(uint4*)(g_q + P*ADn + 8) = *(uint4*)&pk[4];
                *(uint4*)(g_k + P*ADn)     = *(uint4*)&pk[8];
                *(uint4*)(g_k + P*ADn + 8) = *(uint4*)&pk[12];
            } else {
                #pragma unroll
                for (int i = 0; i < 16; i++) pk[i] = pack2h(acc[2*i], acc[2*i+1]);
                #pragma unroll
                for (int q = 0; q < 4; q++)
                    *(uint4*)(g_v + P*SCn + q*8) = *(uint4*)&pk[4*q];
            }
        } else {
            int c0 = cg*32;
            __align__(16) uint32_t pk[8];
            #pragma unroll
            for (int i = 0; i < 8; i++) {
                int c = sub*16 + 2*i;
                pk[i] = pack2h(tb[c*132 + p]*sgall[c0+c], tb[(c+1)*132 + p]*sgall[c0+c+1]);
            }
            *(uint4*)(g_y + P*Cn + c0 + sub*16)     = *(uint4*)&pk[0];
            *(uint4*)(g_y + P*Cn + c0 + sub*16 + 8) = *(uint4*)&pk[4];
        }
        __syncthreads();
    }
}

// ======================= kernel 3: flash attention, max-free softmax ===============
#define ATT_Q   0
#define ATT_K0  1536
#define ATT_K1  4608
#define ATT_V0  7680
#define ATT_V1  12800
#define ATT_PW  17920
#define ATT_SMEM_BYTES (19200*2)   // 38400

__global__ __launch_bounds__(128) void attn_mma_kernel(
    const float* __restrict__ proj_w, const float* __restrict__ proj_b)
{
    extern __shared__ __half smb[];
    const uint32_t sb = smem_to_u32(smb);
    const int tid = threadIdx.x, lane = tid & 31, wid = tid >> 5;
    const int b = blockIdx.y;
    const int m0 = blockIdx.x*64;
    const size_t pixbase = (size_t)b*HWn + m0;

    { // stage Q (64 rows) + proj weights
        int row = tid >> 1, half = tid & 1;
        *(uint4*)(smb + ATT_Q + row*24 + half*8) = *(const uint4*)(g_q + (pixbase + row)*ADn + half*8);
    }
    for (int i = tid; i < SCn*SCn; i += 128) {
        int o = i >> 5, c = i & 31;
        smb[ATT_PW + o*40 + c] = __float2half_rn(proj_w[i]);
    }

    auto ISSUE_KV = [&](int kc, int buf) {
        size_t kb = (size_t)b*HWn + kc*128;
        #pragma unroll
        for (int q = 0; q < 2; q++) {
            int idx = tid + q*128;
            int row = idx >> 1, half = idx & 1;
            uint32_t kdst = sb + (uint32_t)((buf ? ATT_K1 : ATT_K0) + row*24 + half*8)*2;
            CP_ASYNC16(kdst, g_k + (kb + row)*ADn + half*8);
        }
        #pragma unroll
        for (int q = 0; q < 4; q++) {
            int idx = tid + q*128;
            int vr = idx >> 2, part = idx & 3;
            uint32_t vdst = sb + (uint32_t)((buf ? ATT_V1 : ATT_V0) + vr*40 + part*8)*2;
            CP_ASYNC16(vdst, g_v + (kb + vr)*SCn + part*8);
        }
    };

    ISSUE_KV(0, 0); CP_COMMIT();
    __syncthreads();

    uint32_t aq[4];
    ldsm_x4(aq, sb + (ATT_Q + (wid*16 + (lane & 15))*24 + (lane >> 4)*8)*2);

    float o_acc[4][4];
    #pragma unroll
    for (int nt = 0; nt < 4; nt++)
        #pragma unroll
        for (int i = 0; i < 4; i++) o_acc[nt][i] = 0.f;
    float lA = 0.f, lB = 0.f;   // per-lane partial softmax denominators

    for (int kc = 0; kc < 8; kc++) {
        int buf = kc & 1;
        if (kc < 7) { ISSUE_KV(kc + 1, buf ^ 1); CP_COMMIT(); CP_WAIT(1); }
        else        { CP_WAIT(0); }
        __syncthreads();
        const uint32_t KB = buf ? ATT_K1 : ATT_K0;
        const uint32_t VB = buf ? ATT_V1 : ATT_V0;

        // S = QK^T
        float s[16][4];
        #pragma unroll
        for (int t = 0; t < 16; t++)
            #pragma unroll
            for (int i = 0; i < 4; i++) s[t][i] = 0.f;

        #pragma unroll
        for (int pr = 0; pr < 8; pr++) {
            uint32_t k4[4];
            ldsm_x4(k4, sb + (KB + (pr*16 + (lane & 15))*24 + (lane >> 4)*8)*2);
            uint32_t b0[2] = {k4[0], k4[2]}, b1[2] = {k4[1], k4[3]};
            mma_f16(s[2*pr],   aq, b0);
            mma_f16(s[2*pr+1], aq, b1);
        }

        // max-free softmax: scores are tiny (|s| << 1), exp is safe in fp32
        #pragma unroll
        for (int t = 0; t < 16; t++) {
            s[t][0] = __expf(s[t][0]);
            s[t][1] = __expf(s[t][1]);
            s[t][2] = __expf(s[t][2]);
            s[t][3] = __expf(s[t][3]);
            lA += s[t][0] + s[t][1];
            lB += s[t][2] + s[t][3];
        }

        // O += P @ V
        #pragma unroll
        for (int j = 0; j < 8; j++) {
            uint32_t ap[4];
            ap[0] = pack2h(s[2*j][0],   s[2*j][1]);
            ap[1] = pack2h(s[2*j][2],   s[2*j][3]);
            ap[2] = pack2h(s[2*j+1][0], s[2*j+1][1]);
            ap[3] = pack2h(s[2*j+1][2], s[2*j+1][3]);
            #pragma unroll
            for (int cb = 0; cb < 2; cb++) {
                uint32_t rv[4];
                ldsm_x4_t(rv, sb + (VB + (j*16 + (lane & 15))*40 + cb*16 + (lane >> 4)*8)*2);
                uint32_t b0[2] = {rv[0], rv[1]}, b1[2] = {rv[2], rv[3]};
                mma_f16(o_acc[cb*2],   ap, b0);
                mma_f16(o_acc[cb*2+1], ap, b1);
            }
        }
        __syncthreads();
    }

    // one final row-sum reduction across the quad (lanes sharing a row)
    #pragma unroll
    for (int off = 1; off < 4; off <<= 1) {
        lA += __shfl_xor_sync(0xffffffffu, lA, off);
        lB += __shfl_xor_sync(0xffffffffu, lB, off);
    }
    float invA = 1.f/lA, invB = 1.f/lB;
    #pragma unroll
    for (int nt = 0; nt < 4; nt++) {
        o_acc[nt][0] *= invA; o_acc[nt][1] *= invA;
        o_acc[nt][2] *= invB; o_acc[nt][3] *= invB;
    }

    // proj (32x32)
    float r[4][4];
    #pragma unroll
    for (int nt = 0; nt < 4; nt++)
        #pragma unroll
        for (int i = 0; i < 4; i++) r[nt][i] = 0.f;

    #pragma unroll
    for (int j = 0; j < 2; j++) {
        uint32_t ao[4];
        ao[0] = pack2h(o_acc[2*j][0],   o_acc[2*j][1]);
        ao[1] = pack2h(o_acc[2*j][2],   o_acc[2*j][3]);
        ao[2] = pack2h(o_acc[2*j+1][0], o_acc[2*j+1][1]);
        ao[3] = pack2h(o_acc[2*j+1][2], o_acc[2*j+1][3]);
        #pragma unroll
        for (int pr = 0; pr < 2; pr++) {
            uint32_t p4[4];
            ldsm_x4(p4, sb + (ATT_PW + (pr*16 + (lane & 15))*40 + j*16 + (lane >> 4)*8)*2);
            uint32_t b0[2] = {p4[0], p4[2]}, b1[2] = {p4[1], p4[3]};
            mma_f16(r[pr*2],   ao, b0);
            mma_f16(r[pr*2+1], ao, b1);
        }
    }

    {
        size_t pA = pixbase + wid*16 + (lane >> 2);
        size_t pB = pA + 8;
        #pragma unroll
        for (int nt = 0; nt < 4; nt++) {
            int col = nt*8 + (lane & 3)*2;
            float b0 = proj_b[col], b1 = proj_b[col+1];
            *(uint32_t*)(g_y + pA*Cn + col) = pack2h(r[nt][0] + b0, r[nt][1] + b1);
            *(uint32_t*)(g_y + pB*Cn + col) = pack2h(r[nt][2] + b0, r[nt][3] + b1);
        }
    }
}

// ======================= kernels 4/5: fp16 GEMM (MTILE templated) =====
#define KCh 32
#define A_STRIDE 40
#define W_STRIDE 136
#define NSTAGE 4

template<int MTILE, int NTOT, int KTOT, int MODE>
__global__ __launch_bounds__(256)
void mma_gemm_kernel(const __half* __restrict__ Ag, const __half* __restrict__ Wg,
                     const float* __restrict__ bias,
                     __half* __restrict__ H, float* __restrict__ Out)
{
    extern __shared__ char smraw[];
    const uint32_t smem_base = smem_to_u32(smraw);

    constexpr int MT = MTILE/64;
    constexpr int OFF_W = MTILE*A_STRIDE*2;
    constexpr int STAGE_BYTES = MTILE*A_STRIDE*2 + KCh*W_STRIDE*2;

    const int tid = threadIdx.x;
    const int lane = tid & 31, wid = tid >> 5;
    const int warp_m = wid & 3;
    const int warp_n = wid >> 2;
    const int m0 = blockIdx.y*MTILE, n0 = blockIdx.x*128;
    constexpr int NC = KTOT / KCh;

    float acc[MT][8][4];
    #pragma unroll
    for (int mt = 0; mt < MT; mt++)
        #pragma unroll
        for (int nt = 0; nt < 8; nt++)
            #pragma unroll
            for (int i = 0; i < 4; i++) acc[mt][nt][i] = 0.f;

    auto ISSUE = [&](int kc, int buf) {
        uint32_t sbase = smem_base + buf*STAGE_BYTES;
        #pragma unroll
        for (int q = 0; q < MT; q++) {
            int idx = tid + q*256;
            int row = idx >> 2, seg = idx & 3;
            uint32_t dst = sbase + row*(A_STRIDE*2) + seg*16;
            const __half* src = Ag + (size_t)(m0 + row)*KTOT + kc*KCh + seg*8;
            CP_ASYNC16(dst, src);
        }
        #pragma unroll
        for (int q = 0; q < 2; q++) {
            int idx = tid + q*256;
            int row = idx >> 4, seg = idx & 15;
            uint32_t dst = sbase + OFF_W + row*(W_STRIDE*2) + seg*16;
            const __half* src = Wg + (size_t)(kc*KCh + row)*NTOT + n0 + seg*8;
            CP_ASYNC16(dst, src);
        }
    };

    auto COMPUTE = [&](int buf) {
        uint32_t sbx = smem_base + buf*STAGE_BYTES;
        #pragma unroll
        for (int ks = 0; ks < 2; ks++) {
            int k0 = ks*16;
            uint32_t a[MT][4];
            #pragma unroll
            for (int mt = 0; mt < MT; mt++) {
                uint32_t off = ((warp_m*(MT*16) + mt*16 + (lane & 15))*A_STRIDE + k0 + ((lane >> 4) << 3))*2;
                ldsm_x4(a[mt], sbx + off);
            }
            #pragma unroll
            for (int np = 0; np < 4; np++) {
                uint32_t off = ((k0 + (lane & 15))*W_STRIDE + warp_n*64 + np*16 + ((lane >> 4) << 3))*2;
                uint32_t rw[4];
                ldsm_x4_t(rw, sbx + OFF_W + off);
                uint32_t b0[2] = {rw[0], rw[1]}, b1[2] = {rw[2], rw[3]};
                #pragma unroll
                for (int mt = 0; mt < MT; mt++) {
                    mma_f16(acc[mt][2*np],   a[mt], b0);
                    mma_f16(acc[mt][2*np+1], a[mt], b1);
                }
            }
        }
    };

    #pragma unroll
    for (int s = 0; s < NSTAGE-1; s++) {
        if (s < NC) ISSUE(s, s);
        CP_COMMIT();
    }
    for (int kc = 0; kc < NC; kc++) {
        CP_WAIT(NSTAGE-2);
        __syncthreads();
        COMPUTE(kc % NSTAGE);
        int nx = kc + NSTAGE - 1;
        if (nx < NC) ISSUE(nx, nx % NSTAGE);
        CP_COMMIT();
    }
    CP_WAIT(0);

    if (MODE == 1) {
        #pragma unroll
        for (int mt = 0; mt < MT; mt++)
            #pragma unroll
            for (int half = 0; half < 2; half++) {
                int row = m0 + warp_m*(MT*16) + mt*16 + (lane >> 2) + half*8;
                #pragma unroll
                for (int nt = 0; nt < 8; nt++) {
                    int col = n0 + warp_n*64 + nt*8 + (lane & 3)*2;
                    float f0 = fmaxf(acc[mt][nt][half*2+0] + bias[col],   0.f);
                    float f1 = fmaxf(acc[mt][nt][half*2+1] + bias[col+1], 0.f);
                    *(uint32_t*)(H + (size_t)row*NTOT + col) = pack2h(f0, f1);
                }
            }
    } else {
        constexpr int MPASS = MTILE/128;
        float* Ct = (float*)smraw;    // [128][129]
        #pragma unroll
        for (int mh = 0; mh < MPASS; mh++) {
            __syncthreads();
            if (MPASS == 1 || (warp_m >> 1) == mh) {
                int wrow = (MPASS == 1) ? warp_m*(MT*16) : (warp_m & 1)*64;
                #pragma unroll
                for (int mt = 0; mt < MT; mt++)
                    #pragma unroll
                    for (int half = 0; half < 2; half++) {
                        int rl = wrow + mt*16 + (lane >> 2) + half*8;
                        #pragma unroll
                        for (int nt = 0; nt < 8; nt++) {
                            int cl = warp_n*64 + nt*8 + (lane & 3)*2;
                            Ct[rl*129 + cl]     = acc[mt][nt][half*2+0];
                            Ct[rl*129 + cl + 1] = acc[mt][nt][half*2+1];
                        }
                    }
            }
            __syncthreads();
            int pix0 = m0 + mh*128;
            int bb = pix0 >> 10, nn0 = pix0 & (HWn-1);
            #pragma unroll
            for (int cc = 0; cc < 16; cc++) {
                int col = wid*16 + cc;
                int co = n0 + col;
                float bi = bias[co];
                float* ob = Out + (size_t)bb*Cn*HWn + (size_t)co*HWn + nn0;
                #pragma unroll
                for (int j = 0; j < 4; j++) {
                    int rr = lane + 32*j;
                    ob[rr] = Ct[rr*129 + col] + bi;
                }
            }
        }
    }
}

#define G1_SMEM (NSTAGE*(256*A_STRIDE*2 + KCh*W_STRIDE*2))   // 116736
#define G2_SMEM (NSTAGE*(128*A_STRIDE*2 + KCh*W_STRIDE*2))   // 75776

// ======================= launch =======================
extern "C" void kernel_launch(void* const* d_in, const int* in_sizes, int n_in,
                              void* d_out, int out_size)
{
    const float* x      = (const float*)d_in[0];
    const float* fc1_w  = (const float*)d_in[1];
    const float* fc1_b  = (const float*)d_in[2];
    const float* fc2_w  = (const float*)d_in[3];
    const float* fc2_b  = (const float*)d_in[4];
    const float* qkv_w  = (const float*)d_in[5];
    const float* qkv_b  = (const float*)d_in[6];
    const float* proj_w = (const float*)d_in[7];
    const float* proj_b = (const float*)d_in[8];
    const float* ffn1_w = (const float*)d_in[9];
    const float* ffn1_b = (const float*)d_in[10];
    const float* ffn2_w = (const float*)d_in[11];
    const float* ffn2_b = (const float*)d_in[12];
    float* out = (float*)d_out;

    cudaFuncSetAttribute(attn_mma_kernel, cudaFuncAttributeMaxDynamicSharedMemorySize, ATT_SMEM_BYTES);
    cudaFuncSetAttribute((const void*)mma_gemm_kernel<256, C4n, Cn, 1>, cudaFuncAttributeMaxDynamicSharedMemorySize, G1_SMEM);
    cudaFuncSetAttribute((const void*)mma_gemm_kernel<128, Cn, C4n, 2>, cudaFuncAttributeMaxDynamicSharedMemorySize, G2_SMEM);

    __half *yp, *hp, *w1, *w2;
    cudaGetSymbolAddress((void**)&yp, g_y);
    cudaGetSymbolAddress((void**)&hp, g_h);
    cudaGetSymbolAddress((void**)&w1, g_w1);
    cudaGetSymbolAddress((void**)&w2, g_w2);

    pre_kernel<<<640, 256>>>(ffn1_w, ffn2_w, x, fc1_w, fc1_b, fc2_w, fc2_b);
    gate_all_kernel<<<dim3(8, Bn), 256>>>(x, qkv_w, qkv_b);
    attn_mma_kernel<<<dim3(16, Bn), 128, ATT_SMEM_BYTES>>>(proj_w, proj_b);

    mma_gemm_kernel<256, C4n, Cn, 1><<<dim3(C4n/128, NPIX/256), 256, G1_SMEM>>>(
        yp, w1, ffn1_b, hp, nullptr);
    mma_gemm_kernel<128, Cn, C4n, 2><<<dim3(Cn/128, NPIX/128), 256, G2_SMEM>>>(
        hp, w2, ffn2_b, nullptr, out);
}

// round 17
// speedup vs baseline: 1.1092x; 1.1092x over previous
#include <cuda_runtime.h>
#include <cuda_fp16.h>
#include <cstdint>
#include <math.h>

#define Bn   16
#define Cn   256
#define HWn  1024
#define ADn  16
#define SCn  32
#define CRn  64
#define C4n  1024
#define NPIX (Bn*HWn)   // 16384

// ======================= device scratch =======================
__device__ float g_part[Bn*8*Cn];
__device__ int   g_cnt[Bn];
__device__ float g_s[Bn*Cn];
__device__ __align__(256) __half g_q[Bn*HWn*ADn];
__device__ __align__(256) __half g_k[Bn*HWn*ADn];
__device__ __align__(256) __half g_v[Bn*HWn*SCn];
__device__ __align__(256) __half g_y[NPIX*Cn];
__device__ __align__(256) __half g_h[NPIX*C4n];
__device__ __align__(256) __half g_w1[Cn*C4n];
__device__ __align__(256) __half g_w2[C4n*Cn];

// ======================= PTX helpers =======================
__device__ __forceinline__ uint32_t smem_to_u32(const void* p) {
    uint32_t a;
    asm("{ .reg .u64 t; cvta.to.shared.u64 t, %1; cvt.u32.u64 %0, t; }" : "=r"(a) : "l"(p));
    return a;
}
__device__ __forceinline__ void ldsm_x4(uint32_t r[4], uint32_t addr) {
    asm volatile("ldmatrix.sync.aligned.m8n8.x4.shared.b16 {%0,%1,%2,%3}, [%4];"
        : "=r"(r[0]), "=r"(r[1]), "=r"(r[2]), "=r"(r[3]) : "r"(addr));
}
__device__ __forceinline__ void ldsm_x4_t(uint32_t r[4], uint32_t addr) {
    asm volatile("ldmatrix.sync.aligned.m8n8.x4.trans.shared.b16 {%0,%1,%2,%3}, [%4];"
        : "=r"(r[0]), "=r"(r[1]), "=r"(r[2]), "=r"(r[3]) : "r"(addr));
}
__device__ __forceinline__ void mma_f16(float c[4], const uint32_t a[4], const uint32_t b[2]) {
    asm volatile("mma.sync.aligned.m16n8k16.row.col.f32.f16.f16.f32 "
        "{%0,%1,%2,%3}, {%4,%5,%6,%7}, {%8,%9}, {%0,%1,%2,%3};"
        : "+f"(c[0]), "+f"(c[1]), "+f"(c[2]), "+f"(c[3])
        : "r"(a[0]), "r"(a[1]), "r"(a[2]), "r"(a[3]), "r"(b[0]), "r"(b[1]));
}
#define CP_ASYNC16(dst, src) \
    asm volatile("cp.async.cg.shared.global [%0], [%1], 16;" :: "r"(dst), "l"(src))
#define CP_COMMIT() asm volatile("cp.async.commit_group;")
#define CP_WAIT(n)  asm volatile("cp.async.wait_group %0;" :: "n"(n))

__device__ __forceinline__ uint32_t pack2h(float f0, float f1) {
    __half2 h = __floats2half2_rn(f0, f1);
    return *(uint32_t*)&h;
}

// ======================= kernel 1: fused convert(512) + SE(128, atomic finisher) =====
__global__ __launch_bounds__(256) void pre_kernel(
    const float* __restrict__ w1f, const float* __restrict__ w2f,
    const float* __restrict__ x,
    const float* __restrict__ fc1_w, const float* __restrict__ fc1_b,
    const float* __restrict__ fc2_w, const float* __restrict__ fc2_b)
{
    int bid = blockIdx.x;
    int tid = threadIdx.x, lane = tid & 31, warp = tid >> 5;

    if (bid < 512) {
        __shared__ float s[32][33];
        const float* w; int O, K, tk, to;
        if (bid < 256) { w = w1f; O = C4n; K = Cn;  tk = bid & 7;  to = bid >> 3; }
        else { int b2 = bid - 256; w = w2f; O = Cn; K = C4n; tk = b2 >> 3; to = b2 & 7; }
        __half* dst = (O == C4n) ? g_w1 : g_w2;
        int k0 = tk*32, o0 = to*32;
        #pragma unroll
        for (int i = tid; i < 1024; i += 256) {
            int o = i >> 5, k = i & 31;
            s[k][o] = w[(size_t)(o0 + o)*K + k0 + k];
        }
        __syncthreads();
        #pragma unroll
        for (int i = tid; i < 1024; i += 256) {
            int k = i >> 5, o = i & 31;
            dst[(size_t)(k0 + k)*O + o0 + o] = __float2half_rn(s[k][o]);
        }
        return;
    }

    int id = bid - 512;
    int sl = id & 7, b = id >> 3;
    #pragma unroll
    for (int c = warp; c < Cn; c += 8) {
        float4 v = *(const float4*)(x + ((size_t)b*Cn + c)*HWn + sl*128 + lane*4);
        float sum = v.x + v.y + v.z + v.w;
        #pragma unroll
        for (int o = 16; o > 0; o >>= 1) sum += __shfl_xor_sync(0xffffffffu, sum, o);
        if (lane == 0) g_part[(b*8 + sl)*Cn + c] = sum;
    }
    __threadfence();
    __shared__ int is_last;
    if (tid == 0) is_last = (atomicAdd(&g_cnt[b], 1) == 7);
    __syncthreads();
    if (!is_last) return;
    if (tid == 0) g_cnt[b] = 0;

    __shared__ float mean[Cn];
    __shared__ float s1[CRn];
    {
        float sum = 0.f;
        #pragma unroll
        for (int s = 0; s < 8; s++) sum += g_part[(b*8 + s)*Cn + tid];
        mean[tid] = sum * (1.0f/HWn);
    }
    __syncthreads();
    #pragma unroll
    for (int i = 0; i < 8; i++) {
        int o = warp*8 + i;
        const float* wr = fc1_w + o*Cn;
        float sum = 0.f;
        #pragma unroll
        for (int j = 0; j < 8; j++) {
            int c = lane + 32*j;
            sum += wr[c]*mean[c];
        }
        #pragma unroll
        for (int off = 16; off > 0; off >>= 1) sum += __shfl_xor_sync(0xffffffffu, sum, off);
        if (lane == 0) s1[o] = fmaxf(sum + fc1_b[o], 0.f);
    }
    __syncthreads();
    #pragma unroll
    for (int i = 0; i < 32; i++) {
        int o = warp*32 + i;
        const float* wr = fc2_w + o*CRn;
        float sum = wr[lane]*s1[lane] + wr[lane+32]*s1[lane+32];
        #pragma unroll
        for (int off = 16; off > 0; off >>= 1) sum += __shfl_xor_sync(0xffffffffu, sum, off);
        if (lane == 0) g_s[b*Cn + o] = 1.f/(1.f + __expf(-(sum + fc2_b[o])));
    }
}

// ======================= kernel 2: fused gate + qkv (cp.async double-buffered) =====
__global__ __launch_bounds__(256) void gate_all_kernel(
    const float* __restrict__ x,
    const float* __restrict__ qkv_w, const float* __restrict__ qkv_b)
{
    __shared__ float t[2*32*132];
    __shared__ float ws[32][64];
    __shared__ float sgall[Cn];
    __shared__ float qb[64];

    int b = blockIdx.y, n0 = blockIdx.x*128;
    int tid = threadIdx.x;
    const uint32_t tbase = smem_to_u32(t);

    auto ISSUE_X = [&](int cg, int buf) {
        #pragma unroll
        for (int q = 0; q < 4; q++) {
            int idx = tid + q*256;
            int row = idx >> 5, seg = idx & 31;
            uint32_t dst = tbase + (uint32_t)(buf*4224 + row*132)*4 + seg*16;
            const float* src = x + ((size_t)b*Cn + cg*32 + row)*HWn + n0 + seg*4;
            CP_ASYNC16(dst, src);
        }
    };

    ISSUE_X(0, 0); CP_COMMIT();

    for (int i = tid; i < 64*SCn; i += 256) { int o = i >> 5, c = i & 31; ws[c][o] = qkv_w[i]; }
    if (tid < 64) qb[tid] = qkv_b[tid];
    sgall[tid] = g_s[b*Cn + tid];

    int p   = tid & 127;
    int sub = tid >> 7;
    size_t P = (size_t)b*HWn + n0 + p;

    for (int cg = 0; cg < 8; cg++) {
        int buf = cg & 1;
        if (cg < 7) { ISSUE_X(cg + 1, buf ^ 1); CP_COMMIT(); CP_WAIT(1); }
        else        { CP_WAIT(0); }
        __syncthreads();
        const float* tb = t + buf*4224;

        if (cg == 0) {
            float acc[32];
            #pragma unroll
            for (int o = 0; o < 32; o++) acc[o] = qb[sub*32 + o];
            #pragma unroll 4
            for (int c = 0; c < SCn; c++) {
                float xv = tb[c*132 + p] * sgall[c];
                #pragma unroll
                for (int o4 = 0; o4 < 8; o4++) {
                    float4 w = *(const float4*)&ws[c][sub*32 + o4*4];
                    acc[o4*4+0] += w.x*xv;
                    acc[o4*4+1] += w.y*xv;
                    acc[o4*4+2] += w.z*xv;
                    acc[o4*4+3] += w.w*xv;
                }
            }
            __align__(16) uint32_t pk[16];
            if (sub == 0) {
                #pragma unroll
                for (int i = 0; i < 8; i++) pk[i] = pack2h(acc[2*i]*0.25f, acc[2*i+1]*0.25f);
                #pragma unroll
                for (int i = 8; i < 16; i++) pk[i] = pack2h(acc[2*i], acc[2*i+1]);
                *(uint4*)(g_q + P*ADn)     = *(uint4*)&pk[0];
                *(uint4*)(g_q + P*ADn + 8) = *(uint4*)&pk[4];
                *(uint4*)(g_k + P*ADn)     = *(uint4*)&pk[8];
                *(uint4*)(g_k + P*ADn + 8) = *(uint4*)&pk[12];
            } else {
                #pragma unroll
                for (int i = 0; i < 16; i++) pk[i] = pack2h(acc[2*i], acc[2*i+1]);
                #pragma unroll
                for (int q = 0; q < 4; q++)
                    *(uint4*)(g_v + P*SCn + q*8) = *(uint4*)&pk[4*q];
            }
        } else {
            int c0 = cg*32;
            __align__(16) uint32_t pk[8];
            #pragma unroll
            for (int i = 0; i < 8; i++) {
                int c = sub*16 + 2*i;
                pk[i] = pack2h(tb[c*132 + p]*sgall[c0+c], tb[(c+1)*132 + p]*sgall[c0+c+1]);
            }
            *(uint4*)(g_y + P*Cn + c0 + sub*16)     = *(uint4*)&pk[0];
            *(uint4*)(g_y + P*Cn + c0 + sub*16 + 8) = *(uint4*)&pk[4];
        }
        __syncthreads();
    }
}

// ======================= kernel 3: flash attention, max-free softmax ===============
#define ATT_Q   0
#define ATT_K0  1536
#define ATT_K1  4608
#define ATT_V0  7680
#define ATT_V1  12800
#define ATT_PW  17920
#define ATT_SMEM_BYTES (19200*2)   // 38400

__global__ __launch_bounds__(128) void attn_mma_kernel(
    const float* __restrict__ proj_w, const float* __restrict__ proj_b)
{
    extern __shared__ __half smb[];
    const uint32_t sb = smem_to_u32(smb);
    const int tid = threadIdx.x, lane = tid & 31, wid = tid >> 5;
    const int b = blockIdx.y;
    const int m0 = blockIdx.x*64;
    const size_t pixbase = (size_t)b*HWn + m0;

    {
        int row = tid >> 1, half = tid & 1;
        *(uint4*)(smb + ATT_Q + row*24 + half*8) = *(const uint4*)(g_q + (pixbase + row)*ADn + half*8);
    }
    for (int i = tid; i < SCn*SCn; i += 128) {
        int o = i >> 5, c = i & 31;
        smb[ATT_PW + o*40 + c] = __float2half_rn(proj_w[i]);
    }

    auto ISSUE_KV = [&](int kc, int buf) {
        size_t kb = (size_t)b*HWn + kc*128;
        #pragma unroll
        for (int q = 0; q < 2; q++) {
            int idx = tid + q*128;
            int row = idx >> 1, half = idx & 1;
            uint32_t kdst = sb + (uint32_t)((buf ? ATT_K1 : ATT_K0) + row*24 + half*8)*2;
            CP_ASYNC16(kdst, g_k + (kb + row)*ADn + half*8);
        }
        #pragma unroll
        for (int q = 0; q < 4; q++) {
            int idx = tid + q*128;
            int vr = idx >> 2, part = idx & 3;
            uint32_t vdst = sb + (uint32_t)((buf ? ATT_V1 : ATT_V0) + vr*40 + part*8)*2;
            CP_ASYNC16(vdst, g_v + (kb + vr)*SCn + part*8);
        }
    };

    ISSUE_KV(0, 0); CP_COMMIT();
    __syncthreads();

    uint32_t aq[4];
    ldsm_x4(aq, sb + (ATT_Q + (wid*16 + (lane & 15))*24 + (lane >> 4)*8)*2);

    float o_acc[4][4];
    #pragma unroll
    for (int nt = 0; nt < 4; nt++)
        #pragma unroll
        for (int i = 0; i < 4; i++) o_acc[nt][i] = 0.f;
    float lA = 0.f, lB = 0.f;

    for (int kc = 0; kc < 8; kc++) {
        int buf = kc & 1;
        if (kc < 7) { ISSUE_KV(kc + 1, buf ^ 1); CP_COMMIT(); CP_WAIT(1); }
        else        { CP_WAIT(0); }
        __syncthreads();
        const uint32_t KB = buf ? ATT_K1 : ATT_K0;
        const uint32_t VB = buf ? ATT_V1 : ATT_V0;

        float s[16][4];
        #pragma unroll
        for (int t = 0; t < 16; t++)
            #pragma unroll
            for (int i = 0; i < 4; i++) s[t][i] = 0.f;

        #pragma unroll
        for (int pr = 0; pr < 8; pr++) {
            uint32_t k4[4];
            ldsm_x4(k4, sb + (KB + (pr*16 + (lane & 15))*24 + (lane >> 4)*8)*2);
            uint32_t b0[2] = {k4[0], k4[2]}, b1[2] = {k4[1], k4[3]};
            mma_f16(s[2*pr],   aq, b0);
            mma_f16(s[2*pr+1], aq, b1);
        }

        #pragma unroll
        for (int t = 0; t < 16; t++) {
            s[t][0] = __expf(s[t][0]);
            s[t][1] = __expf(s[t][1]);
            s[t][2] = __expf(s[t][2]);
            s[t][3] = __expf(s[t][3]);
            lA += s[t][0] + s[t][1];
            lB += s[t][2] + s[t][3];
        }

        #pragma unroll
        for (int j = 0; j < 8; j++) {
            uint32_t ap[4];
            ap[0] = pack2h(s[2*j][0],   s[2*j][1]);
            ap[1] = pack2h(s[2*j][2],   s[2*j][3]);
            ap[2] = pack2h(s[2*j+1][0], s[2*j+1][1]);
            ap[3] = pack2h(s[2*j+1][2], s[2*j+1][3]);
            #pragma unroll
            for (int cb = 0; cb < 2; cb++) {
                uint32_t rv[4];
                ldsm_x4_t(rv, sb + (VB + (j*16 + (lane & 15))*40 + cb*16 + (lane >> 4)*8)*2);
                uint32_t b0[2] = {rv[0], rv[1]}, b1[2] = {rv[2], rv[3]};
                mma_f16(o_acc[cb*2],   ap, b0);
                mma_f16(o_acc[cb*2+1], ap, b1);
            }
        }
        __syncthreads();
    }

    #pragma unroll
    for (int off = 1; off < 4; off <<= 1) {
        lA += __shfl_xor_sync(0xffffffffu, lA, off);
        lB += __shfl_xor_sync(0xffffffffu, lB, off);
    }
    float invA = 1.f/lA, invB = 1.f/lB;
    #pragma unroll
    for (int nt = 0; nt < 4; nt++) {
        o_acc[nt][0] *= invA; o_acc[nt][1] *= invA;
        o_acc[nt][2] *= invB; o_acc[nt][3] *= invB;
    }

    float r[4][4];
    #pragma unroll
    for (int nt = 0; nt < 4; nt++)
        #pragma unroll
        for (int i = 0; i < 4; i++) r[nt][i] = 0.f;

    #pragma unroll
    for (int j = 0; j < 2; j++) {
        uint32_t ao[4];
        ao[0] = pack2h(o_acc[2*j][0],   o_acc[2*j][1]);
        ao[1] = pack2h(o_acc[2*j][2],   o_acc[2*j][3]);
        ao[2] = pack2h(o_acc[2*j+1][0], o_acc[2*j+1][1]);
        ao[3] = pack2h(o_acc[2*j+1][2], o_acc[2*j+1][3]);
        #pragma unroll
        for (int pr = 0; pr < 2; pr++) {
            uint32_t p4[4];
            ldsm_x4(p4, sb + (ATT_PW + (pr*16 + (lane & 15))*40 + j*16 + (lane >> 4)*8)*2);
            uint32_t b0[2] = {p4[0], p4[2]}, b1[2] = {p4[1], p4[3]};
            mma_f16(r[pr*2],   ao, b0);
            mma_f16(r[pr*2+1], ao, b1);
        }
    }

    {
        size_t pA = pixbase + wid*16 + (lane >> 2);
        size_t pB = pA + 8;
        #pragma unroll
        for (int nt = 0; nt < 4; nt++) {
            int col = nt*8 + (lane & 3)*2;
            float b0 = proj_b[col], b1 = proj_b[col+1];
            *(uint32_t*)(g_y + pA*Cn + col) = pack2h(r[nt][0] + b0, r[nt][1] + b1);
            *(uint32_t*)(g_y + pB*Cn + col) = pack2h(r[nt][2] + b0, r[nt][3] + b1);
        }
    }
}

// ======================= kernels 4/5: fp16 GEMM 128x128, 2 CTAs/SM =====
#define KCh 32
#define A_STRIDE 40
#define W_STRIDE 136
#define NSTAGE 4
#define MTILE 128
#define OFF_W (MTILE*A_STRIDE*2)
#define STAGE_BYTES (MTILE*A_STRIDE*2 + KCh*W_STRIDE*2)   // 18944
#define GEMM_SMEM (NSTAGE*STAGE_BYTES)                    // 75776

template<int NTOT, int KTOT, int MODE>
__global__ __launch_bounds__(256, 2)
void mma_gemm_kernel(const __half* __restrict__ Ag, const __half* __restrict__ Wg,
                     const float* __restrict__ bias,
                     __half* __restrict__ H, float* __restrict__ Out)
{
    extern __shared__ char smraw[];
    const uint32_t smem_base = smem_to_u32(smraw);

    const int tid = threadIdx.x;
    const int lane = tid & 31, wid = tid >> 5;
    const int warp_m = wid & 3;               // 4 warps over M (32 rows)
    const int warp_n = wid >> 2;              // 2 warps over N (64 cols)
    const int m0 = blockIdx.y*MTILE, n0 = blockIdx.x*128;
    constexpr int NC = KTOT / KCh;

    float acc[2][8][4];
    #pragma unroll
    for (int mt = 0; mt < 2; mt++)
        #pragma unroll
        for (int nt = 0; nt < 8; nt++)
            #pragma unroll
            for (int i = 0; i < 4; i++) acc[mt][nt][i] = 0.f;

    auto ISSUE = [&](int kc, int buf) {
        uint32_t sbase = smem_base + buf*STAGE_BYTES;
        #pragma unroll
        for (int q = 0; q < 2; q++) {
            int idx = tid + q*256;
            int row = idx >> 2, seg = idx & 3;
            uint32_t dst = sbase + row*(A_STRIDE*2) + seg*16;
            const __half* src = Ag + (size_t)(m0 + row)*KTOT + kc*KCh + seg*8;
            CP_ASYNC16(dst, src);
        }
        #pragma unroll
        for (int q = 0; q < 2; q++) {
            int idx = tid + q*256;
            int row = idx >> 4, seg = idx & 15;
            uint32_t dst = sbase + OFF_W + row*(W_STRIDE*2) + seg*16;
            const __half* src = Wg + (size_t)(kc*KCh + row)*NTOT + n0 + seg*8;
            CP_ASYNC16(dst, src);
        }
    };

    auto COMPUTE = [&](int buf) {
        uint32_t sbx = smem_base + buf*STAGE_BYTES;
        #pragma unroll
        for (int ks = 0; ks < 2; ks++) {
            int k0 = ks*16;
            uint32_t a[2][4];
            #pragma unroll
            for (int mt = 0; mt < 2; mt++) {
                uint32_t off = ((warp_m*32 + mt*16 + (lane & 15))*A_STRIDE + k0 + ((lane >> 4) << 3))*2;
                ldsm_x4(a[mt], sbx + off);
            }
            #pragma unroll
            for (int np = 0; np < 4; np++) {
                uint32_t off = ((k0 + (lane & 15))*W_STRIDE + warp_n*64 + np*16 + ((lane >> 4) << 3))*2;
                uint32_t rw[4];
                ldsm_x4_t(rw, sbx + OFF_W + off);
                uint32_t b0[2] = {rw[0], rw[1]}, b1[2] = {rw[2], rw[3]};
                #pragma unroll
                for (int mt = 0; mt < 2; mt++) {
                    mma_f16(acc[mt][2*np],   a[mt], b0);
                    mma_f16(acc[mt][2*np+1], a[mt], b1);
                }
            }
        }
    };

    #pragma unroll
    for (int s = 0; s < NSTAGE-1; s++) {
        if (s < NC) ISSUE(s, s);
        CP_COMMIT();
    }
    for (int kc = 0; kc < NC; kc++) {
        CP_WAIT(NSTAGE-2);
        __syncthreads();
        COMPUTE(kc % NSTAGE);
        int nx = kc + NSTAGE - 1;
        if (nx < NC) ISSUE(nx, nx % NSTAGE);
        CP_COMMIT();
    }
    CP_WAIT(0);

    if (MODE == 1) {
        #pragma unroll
        for (int mt = 0; mt < 2; mt++)
            #pragma unroll
            for (int half = 0; half < 2; half++) {
                int row = m0 + warp_m*32 + mt*16 + (lane >> 2) + half*8;
                #pragma unroll
                for (int nt = 0; nt < 8; nt++) {
                    int col = n0 + warp_n*64 + nt*8 + (lane & 3)*2;
                    float f0 = fmaxf(acc[mt][nt][half*2+0] + bias[col],   0.f);
                    float f1 = fmaxf(acc[mt][nt][half*2+1] + bias[col+1], 0.f);
                    *(uint32_t*)(H + (size_t)row*NTOT + col) = pack2h(f0, f1);
                }
            }
    } else {
        __syncthreads();
        float* Ct = (float*)smraw;    // [128][129]
        #pragma unroll
        for (int mt = 0; mt < 2; mt++)
            #pragma unroll
            for (int half = 0; half < 2; half++) {
                int rl = warp_m*32 + mt*16 + (lane >> 2) + half*8;
                #pragma unroll
                for (int nt = 0; nt < 8; nt++) {
                    int cl = warp_n*64 + nt*8 + (lane & 3)*2;
                    Ct[rl*129 + cl]     = acc[mt][nt][half*2+0];
                    Ct[rl*129 + cl + 1] = acc[mt][nt][half*2+1];
                }
            }
        __syncthreads();
        int bb = m0 >> 10, nn0 = m0 & (HWn-1);
        #pragma unroll
        for (int cc = 0; cc < 16; cc++) {
            int col = wid*16 + cc;
            int co = n0 + col;
            float bi = bias[co];
            float* ob = Out + (size_t)bb*Cn*HWn + (size_t)co*HWn + nn0;
            #pragma unroll
            for (int j = 0; j < 4; j++) {
                int rr = lane + 32*j;
                ob[rr] = Ct[rr*129 + col] + bi;
            }
        }
    }
}

// ======================= launch =======================
extern "C" void kernel_launch(void* const* d_in, const int* in_sizes, int n_in,
                              void* d_out, int out_size)
{
    const float* x      = (const float*)d_in[0];
    const float* fc1_w  = (const float*)d_in[1];
    const float* fc1_b  = (const float*)d_in[2];
    const float* fc2_w  = (const float*)d_in[3];
    const float* fc2_b  = (const float*)d_in[4];
    const float* qkv_w  = (const float*)d_in[5];
    const float* qkv_b  = (const float*)d_in[6];
    const float* proj_w = (const float*)d_in[7];
    const float* proj_b = (const float*)d_in[8];
    const float* ffn1_w = (const float*)d_in[9];
    const float* ffn1_b = (const float*)d_in[10];
    const float* ffn2_w = (const float*)d_in[11];
    const float* ffn2_b = (const float*)d_in[12];
    float* out = (float*)d_out;

    cudaFuncSetAttribute(attn_mma_kernel, cudaFuncAttributeMaxDynamicSharedMemorySize, ATT_SMEM_BYTES);
    cudaFuncSetAttribute((const void*)mma_gemm_kernel<C4n, Cn, 1>, cudaFuncAttributeMaxDynamicSharedMemorySize, GEMM_SMEM);
    cudaFuncSetAttribute((const void*)mma_gemm_kernel<Cn, C4n, 2>, cudaFuncAttributeMaxDynamicSharedMemorySize, GEMM_SMEM);

    __half *yp, *hp, *w1, *w2;
    cudaGetSymbolAddress((void**)&yp, g_y);
    cudaGetSymbolAddress((void**)&hp, g_h);
    cudaGetSymbolAddress((void**)&w1, g_w1);
    cudaGetSymbolAddress((void**)&w2, g_w2);

    pre_kernel<<<640, 256>>>(ffn1_w, ffn2_w, x, fc1_w, fc1_b, fc2_w, fc2_b);
    gate_all_kernel<<<dim3(8, Bn), 256>>>(x, qkv_w, qkv_b);
    attn_mma_kernel<<<dim3(16, Bn), 128, ATT_SMEM_BYTES>>>(proj_w, proj_b);

    mma_gemm_kernel<C4n, Cn, 1><<<dim3(C4n/128, NPIX/128), 256, GEMM_SMEM>>>(
        yp, w1, ffn1_b, hp, nullptr);
    mma_gemm_kernel<Cn, C4n, 2><<<dim3(Cn/128, NPIX/128), 256, GEMM_SMEM>>>(
        hp, w2, ffn2_b, nullptr, out);
}